// round 17
// baseline (speedup 1.0000x reference)
#include <cuda_runtime.h>
#include <cuda_fp16.h>
#include <mma.h>
#include <math.h>

using namespace nvcuda;

// Problem constants (fixed by the dataset)
#define E_NUM 32768
#define BATCH 128     // == H
#define DIM   1024    // IMG_DIM == TXT_DIM
#define KC    64      // GEMM k-chunk within a k-split
#define ASTR  264     // padded smem A row stride (halves): 256 + 8
#define BSTR  72      // padded smem B row stride (halves): 64 + 8
#define WSTR  136     // padded W1 smem stride (halves)
// gemm smem: A 128*ASTR*2 + B 2 bufs * 64*BSTR*2
#define GEMM_SMEM (128 * ASTR * 2 + 2 * 64 * BSTR * 2)   // 86016 B

// ---- device scratch (allocation-free: __device__ globals) ----
__device__ __align__(16) __half g_UTh[DIM * BATCH];   // U^T [s][j] fp16
__device__ __align__(16) __half g_VTh[DIM * BATCH];   // V^T [t][j] fp16
__device__ __align__(16) __half g_P0 [DIM * DIM];     // P0[t][i] = a(i,t)

// ---- UV via tensor cores, self-sufficient (FIRST kernel, no sync) ----
// U[j][s] = sum_b W1a[j][b]*img[b][s] (V analogous; b1 added in k_edge).
// Converts its own W1 half + feature tile fp32->fp16 in smem; zeroes P0 slice.
// grid (64 s-tiles, 2 sides) = 128 blocks, 256 thr (8 warps).
__global__ void __launch_bounds__(256) k_uvw(const float* __restrict__ img,
                                             const float* __restrict__ txt,
                                             const float* __restrict__ W1) {
    __shared__ __align__(16) __half sW[128 * WSTR];   // W1 side [j][b]
    __shared__ __align__(16) __half sF[128 * 16];     // feature tile [b][sc]
    __shared__ __align__(16) float  eps[8][16 * 16];

    int s0   = blockIdx.x * 16;
    int side = blockIdx.y;             // 0: U from img/W1a; 1: V from txt/W1b
    int tid  = threadIdx.x;
    int w    = tid >> 5;
    int lane = tid & 31;

    // zero P0 slice: 2MB / 128 blocks = 1024 float4 per block (4/thread)
    {
        int bid = side * 64 + blockIdx.x;
        float4 z = make_float4(0.f, 0.f, 0.f, 0.f);
        float4* p0 = reinterpret_cast<float4*>(g_P0) + bid * 1024;
#pragma unroll
        for (int i = 0; i < 4; ++i)
            p0[i * 256 + tid] = z;
    }

    // convert W1 half: [128][128] fp32 -> sW fp16 (4096 float4, 16/thread)
    const float* Wsrc = W1 + side * BATCH;
#pragma unroll
    for (int i = 0; i < 16; ++i) {
        int g  = tid + i * 256;
        int r  = g >> 5;
        int c4 = g & 31;
        float4 v = *reinterpret_cast<const float4*>(Wsrc + r * 2 * BATCH + c4 * 4);
        __half2 h01 = __floats2half2_rn(v.x, v.y);
        __half2 h23 = __floats2half2_rn(v.z, v.w);
        uint2 o = make_uint2(*reinterpret_cast<unsigned*>(&h01),
                             *reinterpret_cast<unsigned*>(&h23));
        *reinterpret_cast<uint2*>(&sW[r * WSTR + c4 * 4]) = o;
    }

    // convert feature tile: rows 0..127, cols [s0,s0+16) (512 float4, 2/thread)
    const float* feat = side ? txt : img;
#pragma unroll
    for (int i = 0; i < 2; ++i) {
        int g  = tid + i * 256;
        int r  = g >> 2;
        int c4 = g & 3;
        float4 v = *reinterpret_cast<const float4*>(feat + (long)r * DIM + s0 + c4 * 4);
        __half2 h01 = __floats2half2_rn(v.x, v.y);
        __half2 h23 = __floats2half2_rn(v.z, v.w);
        uint2 o = make_uint2(*reinterpret_cast<unsigned*>(&h01),
                             *reinterpret_cast<unsigned*>(&h23));
        *reinterpret_cast<uint2*>(&sF[r * 16 + c4 * 4]) = o;
    }
    __syncthreads();

    wmma::fragment<wmma::accumulator, 16, 16, 16, float> acc;
    wmma::fill_fragment(acc, 0.0f);
#pragma unroll
    for (int k = 0; k < 8; ++k) {
        wmma::fragment<wmma::matrix_a, 16, 16, 16, __half, wmma::row_major> a;
        wmma::fragment<wmma::matrix_b, 16, 16, 16, __half, wmma::row_major> b;
        wmma::load_matrix_sync(a, &sW[(w * 16) * WSTR + k * 16], WSTR);
        wmma::load_matrix_sync(b, &sF[(k * 16) * 16], 16);
        wmma::mma_sync(acc, a, b, acc);
    }

    wmma::store_matrix_sync(eps[w], acc, 16, wmma::mem_col_major);
    __syncwarp();
    int s  = lane >> 1;
    int j0 = (lane & 1) * 8;
    __half* O = side ? g_VTh : g_UTh;
    const float* sp = eps[w] + s * 16 + j0;
    __half2 h0 = __floats2half2_rn(sp[0], sp[1]);
    __half2 h1 = __floats2half2_rn(sp[2], sp[3]);
    __half2 h2 = __floats2half2_rn(sp[4], sp[5]);
    __half2 h3 = __floats2half2_rn(sp[6], sp[7]);
    uint4 o = make_uint4(*reinterpret_cast<unsigned*>(&h0),
                         *reinterpret_cast<unsigned*>(&h1),
                         *reinterpret_cast<unsigned*>(&h2),
                         *reinterpret_cast<unsigned*>(&h3));
    *reinterpret_cast<uint4*>(O + (long)(s0 + s) * BATCH + w * 16 + j0) = o;
}

// ---- per-edge attention -> P0 only (single 2B store per edge) ----
// Pre-sync side-work: d_out zeroing.
__global__ void k_edge(const int* __restrict__ src, const int* __restrict__ tgt,
                       const float* __restrict__ w2, const float* __restrict__ b1,
                       const float* __restrict__ b2, float* __restrict__ out) {
    int tid  = threadIdx.x;
    int warp = tid >> 5;
    int lane = tid & 31;
    int e    = blockIdx.x * 8 + warp;

    // pre-sync: zero d_out (65536 float4 / 4096 blocks = 16/block)
    if (tid < 16) {
        int g = blockIdx.x * 16 + tid;
        reinterpret_cast<float4*>(out)[g] = make_float4(0.f, 0.f, 0.f, 0.f);
    }

    int s = src[e];
    int t = tgt[e];
    float4 w  = reinterpret_cast<const float4*>(w2)[lane];
    float4 bb = reinterpret_cast<const float4*>(b1)[lane];
    float bias2 = b2[0];

    cudaGridDependencySynchronize();   // wait for k_uvw (UTh/VTh + P0 zeroing)

    uint2 ur = reinterpret_cast<const uint2*>(g_UTh + s * BATCH)[lane];
    uint2 vr = reinterpret_cast<const uint2*>(g_VTh + t * BATCH)[lane];
    float2 u01 = __half22float2(*reinterpret_cast<__half2*>(&ur.x));
    float2 u23 = __half22float2(*reinterpret_cast<__half2*>(&ur.y));
    float2 v01 = __half22float2(*reinterpret_cast<__half2*>(&vr.x));
    float2 v23 = __half22float2(*reinterpret_cast<__half2*>(&vr.y));

    float h0 = fmaxf(u01.x + v01.x + bb.x, 0.0f);
    float h1 = fmaxf(u01.y + v01.y + bb.y, 0.0f);
    float h2 = fmaxf(u23.x + v23.x + bb.z, 0.0f);
    float h3 = fmaxf(u23.y + v23.y + bb.w, 0.0f);

    float p = fmaf(h0, w.x, fmaf(h1, w.y, fmaf(h2, w.z, h3 * w.w)));
#pragma unroll
    for (int off = 16; off; off >>= 1)
        p += __shfl_xor_sync(0xffffffffu, p, off);

    if (lane == 0) {
        float a = __fdividef(1.0f, 1.0f + __expf(-(p + bias2)));
        g_P0[t * DIM + s] = __float2half_rn(a);
    }
}

// ---- split-K tensor-core GEMM; A converted pre-sync, B from P0 both sides --
// side 0: out_img[b][i] = sum_t txt[b][t] * P0[t][i]   (B row-major)
// side 1: out_txt[b][t] = sum_i img[b][i] * P0[t][i]   (B col-major!)
// grid (16 ntiles, 4 ksplits, 2 sides) = 128 blocks, 256 thr (8 warps).
__global__ void __launch_bounds__(256) k_gemm(const float* __restrict__ img,
                                              const float* __restrict__ txt,
                                              float* __restrict__ out) {
    extern __shared__ __align__(16) __half dyn[];
    __half* sA  = dyn;                     // [128][ASTR] (persistent)
    __half* shB = dyn + 128 * ASTR;        // [2][64*BSTR]

    int nt   = blockIdx.x;
    int ksp  = blockIdx.y;
    int side = blockIdx.z;
    int tid  = threadIdx.x;
    int w    = tid >> 5;
    int lane = tid & 31;

    float* C = out + (size_t)side * BATCH * DIM;
    int col0 = nt * 64;
    int k0   = ksp * 256;

    // ---- pre-sync: convert this block's A slice fp32->fp16 smem ----
    // A = (side ? img : txt), rows 0..127, cols [k0, k0+256): 8192 float4
    {
        const float* Af = side ? img : txt;
#pragma unroll
        for (int i = 0; i < 32; ++i) {
            int g  = tid + i * 256;        // 0..8191
            int m  = g >> 6;               // 64 float4 per row
            int c4 = g & 63;
            float4 v = *reinterpret_cast<const float4*>(Af + (long)m * DIM + k0 + c4 * 4);
            __half2 h01 = __floats2half2_rn(v.x, v.y);
            __half2 h23 = __floats2half2_rn(v.z, v.w);
            uint2 o = make_uint2(*reinterpret_cast<unsigned*>(&h01),
                                 *reinterpret_cast<unsigned*>(&h23));
            *reinterpret_cast<uint2*>(&sA[m * ASTR + c4 * 4]) = o;
        }
    }
    __syncthreads();

    cudaGridDependencySynchronize();   // wait for k_edge's P0 writes

    // B staging from P0 (both sides):
    // side 0: tile rows = t = kb+r,   cols = i = col0+nn   (k-major rows)
    // side 1: tile rows = t = col0+r, cols = i = kb+nn     (n-major rows)
    auto stage = [&](int kc, int buf) {
        int kb = k0 + kc * KC;
        int row0 = side ? col0 : kb;
        int cc0  = side ? kb   : col0;
#pragma unroll
        for (int j = 0; j < 2; ++j) {
            int i  = tid + j * 256;
            int r  = i >> 3;
            int nn = (i & 7) * 8;
            unsigned sb = (unsigned)__cvta_generic_to_shared(
                &shB[buf * 64 * BSTR + r * BSTR + nn]);
            const __half* g = g_P0 + (long)(row0 + r) * DIM + cc0 + nn;
            asm volatile("cp.async.cg.shared.global [%0], [%1], 16;" :: "r"(sb), "l"(g));
        }
        asm volatile("cp.async.commit_group;");
    };

    wmma::fragment<wmma::accumulator, 16, 16, 16, float> c[4];
#pragma unroll
    for (int i = 0; i < 4; ++i) wmma::fill_fragment(c[i], 0.0f);

    stage(0, 0);
    for (int kc = 0; kc < 4; ++kc) {
        int buf = kc & 1;
        if (kc < 3) {
            stage(kc + 1, buf ^ 1);
            asm volatile("cp.async.wait_group 1;" ::: "memory");
        } else {
            asm volatile("cp.async.wait_group 0;" ::: "memory");
        }
        __syncthreads();

        if (side == 0) {
#pragma unroll
            for (int ks = 0; ks < KC / 16; ++ks) {
                wmma::fragment<wmma::matrix_a, 16, 16, 16, __half, wmma::row_major> a;
                wmma::load_matrix_sync(a, &sA[(w * 16) * ASTR + kc * KC + ks * 16], ASTR);
#pragma unroll
                for (int cf = 0; cf < 4; ++cf) {
                    wmma::fragment<wmma::matrix_b, 16, 16, 16, __half, wmma::row_major> b;
                    wmma::load_matrix_sync(b, &shB[buf * 64 * BSTR + (ks * 16) * BSTR + cf * 16], BSTR);
                    wmma::mma_sync(c[cf], a, b, c[cf]);
                }
            }
        } else {
#pragma unroll
            for (int ks = 0; ks < KC / 16; ++ks) {
                wmma::fragment<wmma::matrix_a, 16, 16, 16, __half, wmma::row_major> a;
                wmma::load_matrix_sync(a, &sA[(w * 16) * ASTR + kc * KC + ks * 16], ASTR);
#pragma unroll
                for (int cf = 0; cf < 4; ++cf) {
                    // B(k,n) = shB[n*BSTR + k] -> col_major
                    wmma::fragment<wmma::matrix_b, 16, 16, 16, __half, wmma::col_major> b;
                    wmma::load_matrix_sync(b, &shB[buf * 64 * BSTR + (cf * 16) * BSTR + ks * 16], BSTR);
                    wmma::mma_sync(c[cf], a, b, c[cf]);
                }
            }
        }
        __syncthreads();
    }

    // epilogue: fragments -> smem (overlays sA, safe after final sync) -> RED
    float* ep = reinterpret_cast<float*>(dyn) + w * (16 * 68);
#pragma unroll
    for (int cf = 0; cf < 4; ++cf)
        wmma::store_matrix_sync(ep + cf * 16, c[cf], 68, wmma::mem_row_major);

    int m0 = w * 16;
#pragma unroll
    for (int it = 0; it < 8; ++it) {
        int idx = lane + it * 32;
        int r  = idx >> 4;
        int c4 = idx & 15;
        float4 v = *reinterpret_cast<const float4*>(ep + r * 68 + c4 * 4);
        float* gp = C + (long)(m0 + r) * DIM + col0 + c4 * 4;
        asm volatile("red.global.v4.f32.add [%0], {%1, %2, %3, %4};"
                     :: "l"(gp), "f"(v.x), "f"(v.y), "f"(v.z), "f"(v.w)
                     : "memory");
    }
}

extern "C" void kernel_launch(void* const* d_in, const int* in_sizes, int n_in,
                              void* d_out, int out_size) {
    const float* img = (const float*)d_in[0];   // [128, 1024]
    const float* txt = (const float*)d_in[1];   // [128, 1024]
    const int*   src = (const int*)  d_in[2];   // [32768]
    const int*   tgt = (const int*)  d_in[3];   // [32768]
    const float* W1  = (const float*)d_in[4];   // [128, 256]
    const float* b1  = (const float*)d_in[5];   // [128]
    const float* w2  = (const float*)d_in[6];   // [128]
    const float* b2  = (const float*)d_in[7];   // [1]
    float* out = (float*)d_out;                 // [2 * 128 * 1024]

    cudaFuncSetAttribute(k_gemm, cudaFuncAttributeMaxDynamicSharedMemorySize, GEMM_SMEM);

    cudaLaunchAttribute attr;
    attr.id = cudaLaunchAttributeProgrammaticStreamSerialization;
    attr.val.programmaticStreamSerializationAllowed = 1;

    // 1) U/V via tensor cores (self-sufficient; zeroes P0)
    {
        cudaLaunchConfig_t cfg = {};
        cfg.gridDim  = dim3(64, 2);
        cfg.blockDim = dim3(256);
        cfg.attrs = &attr;
        cfg.numAttrs = 1;
        cudaLaunchKernelEx(&cfg, k_uvw, img, txt, W1);
    }

    // 2) per-edge MLP -> P0; pre-sync: d_out zeroing
    {
        cudaLaunchConfig_t cfg = {};
        cfg.gridDim  = dim3(E_NUM / 8);
        cfg.blockDim = dim3(256);
        cfg.attrs = &attr;
        cfg.numAttrs = 1;
        cudaLaunchKernelEx(&cfg, k_edge, src, tgt, w2, b1, b2, out);
    }

    // 3) split-K tensor-core GEMMs (A converted pre-sync) -> RED into d_out
    {
        cudaLaunchConfig_t cfg = {};
        cfg.gridDim  = dim3(16, 4, 2);
        cfg.blockDim = dim3(256);
        cfg.dynamicSmemBytes = GEMM_SMEM;
        cfg.attrs = &attr;
        cfg.numAttrs = 1;
        cudaLaunchKernelEx(&cfg, k_gemm, img, txt, out);
    }
}